// round 11
// baseline (speedup 1.0000x reference)
#include <cuda_runtime.h>
#include <cuda_bf16.h>
#include <stdint.h>

#define NN 4096
#define DD 256
#define BM 128
#define BN 128
#define SA 264          // bf16 elems per padded smem row (256+8)
#define NCHUNKS 32
#define NROWT   32
#define NUNITS  (NCHUNKS * NROWT)
#define GRID 148
#define INV_T 14.285714285714286f

// Bit layout (producer+consumer agree): row-major rows; per row 128 u32 words.
// Chunk ch (128 cols) -> words ch*4 + j (j=0..3); word j, bit b  <=>  col = ch*128 + b*4 + j.
__device__ __nv_bfloat16 g_fn[NN * DD];
__device__ uint32_t g_pmBits[NN * 128];
__device__ uint32_t g_nmBits[NN * 128];
__device__ float g_negP[NCHUNKS * 2 * NN];
__device__ float g_pcsP[NCHUNKS * 2 * NN];
__device__ float g_cntP[NCHUNKS * 2 * NN];
__device__ float g_blockSum[16];
__device__ unsigned g_ctr = 0;   // self-resetting via atomicInc wrap

// ---------------------------------------------------------------------------
__device__ __forceinline__ float fast_expf(float x) {
    float y = x * 1.4426950408889634f;
    float n = rintf(y);
    float f = y - n;
    float p = 1.3333558146e-3f;
    p = fmaf(p, f, 9.6181291076e-3f);
    p = fmaf(p, f, 5.5504108664e-2f);
    p = fmaf(p, f, 2.4022650696e-1f);
    p = fmaf(p, f, 6.9314718056e-1f);
    p = fmaf(p, f, 1.0f);
    int ni = (int)n;
    return p * __int_as_float((ni + 127) << 23);
}

__device__ __forceinline__ void cp16(void* s, const void* g) {
    uint32_t sa = (uint32_t)__cvta_generic_to_shared(s);
    asm volatile("cp.async.cg.shared.global [%0], [%1], 16;\n" :: "r"(sa), "l"(g));
}
__device__ __forceinline__ void cp_commit()  { asm volatile("cp.async.commit_group;\n" ::: "memory"); }
__device__ __forceinline__ void cp_wait_all(){ asm volatile("cp.async.wait_group 0;\n" ::: "memory"); }

__device__ __forceinline__ void ldsm_x4(uint32_t& r0, uint32_t& r1, uint32_t& r2,
                                        uint32_t& r3, uint32_t saddr) {
    asm volatile("ldmatrix.sync.aligned.m8n8.x4.shared.b16 {%0,%1,%2,%3}, [%4];"
                 : "=r"(r0), "=r"(r1), "=r"(r2), "=r"(r3) : "r"(saddr));
}

// ---------------------------------------------------------------------------
// Kernel 1: fused prep.
//  Blocks 0..511: row-normalize -> bf16 g_fn (8 rows/block).
//  Blocks 512..1023: pack masks -> strided bit layout (8 rows/block, 1 row/warp).
// ---------------------------------------------------------------------------
__global__ void __launch_bounds__(256)
prep_kernel(const float* __restrict__ f,
            const float* __restrict__ pmask, const float* __restrict__ nmask) {
    const int tid  = threadIdx.x;
    const int lane = tid & 31;
    const int warp = tid >> 5;

    if (blockIdx.x < 512) {
        int row = blockIdx.x * 8 + warp;
        const float4* src = (const float4*)(f + (size_t)row * DD);
        float4 v0 = src[lane * 2];
        float4 v1 = src[lane * 2 + 1];
        float ss = v0.x * v0.x;
        ss = fmaf(v0.y, v0.y, ss); ss = fmaf(v0.z, v0.z, ss); ss = fmaf(v0.w, v0.w, ss);
        ss = fmaf(v1.x, v1.x, ss); ss = fmaf(v1.y, v1.y, ss);
        ss = fmaf(v1.z, v1.z, ss); ss = fmaf(v1.w, v1.w, ss);
#pragma unroll
        for (int o = 16; o; o >>= 1) ss += __shfl_xor_sync(0xffffffffu, ss, o);
        float s = 1.0f / fmaxf(sqrtf(ss), 1e-8f);
        __nv_bfloat162 h[4];
        h[0] = __floats2bfloat162_rn(v0.x * s, v0.y * s);
        h[1] = __floats2bfloat162_rn(v0.z * s, v0.w * s);
        h[2] = __floats2bfloat162_rn(v1.x * s, v1.y * s);
        h[3] = __floats2bfloat162_rn(v1.z * s, v1.w * s);
        *(uint4*)&g_fn[(size_t)row * DD + lane * 8] = *(uint4*)h;
    } else {
        // one warp per row; per 128-col chunk: float4/thread -> 4 ballots -> uint4 store
        int row = (blockIdx.x - 512) * 8 + warp;
        const float4* pmR = (const float4*)(pmask + (size_t)row * NN);
        const float4* nmR = (const float4*)(nmask + (size_t)row * NN);
        uint4* pDst = (uint4*)&g_pmBits[row * 128];
        uint4* nDst = (uint4*)&g_nmBits[row * 128];
#pragma unroll 4
        for (int ch = 0; ch < 32; ch++) {
            float4 pv = __ldcs(pmR + ch * 32 + lane);
            float4 nv = __ldcs(nmR + ch * 32 + lane);
            uint32_t p0 = __ballot_sync(0xffffffffu, pv.x != 0.f);
            uint32_t p1 = __ballot_sync(0xffffffffu, pv.y != 0.f);
            uint32_t p2 = __ballot_sync(0xffffffffu, pv.z != 0.f);
            uint32_t p3 = __ballot_sync(0xffffffffu, pv.w != 0.f);
            uint32_t n0 = __ballot_sync(0xffffffffu, nv.x != 0.f);
            uint32_t n1 = __ballot_sync(0xffffffffu, nv.y != 0.f);
            uint32_t n2 = __ballot_sync(0xffffffffu, nv.z != 0.f);
            uint32_t n3 = __ballot_sync(0xffffffffu, nv.w != 0.f);
            if (lane == 0) {
                pDst[ch] = make_uint4(p0, p1, p2, p3);
                nDst[ch] = make_uint4(n0, n1, n2, n3);
            }
        }
    }
}

// ---------------------------------------------------------------------------
// Kernel 2: persistent mma.sync GEMM (ldmatrix frags) + in-register bit epilogue.
// ---------------------------------------------------------------------------
__global__ void __launch_bounds__(256, 1)
ssntx_main_kernel() {
    extern __shared__ unsigned char smem[];
    __nv_bfloat16* As = (__nv_bfloat16*)smem;
    __nv_bfloat16* B0 = (__nv_bfloat16*)(smem + BM * SA * 2);
    __nv_bfloat16* B1 = (__nv_bfloat16*)(smem + 2 * BM * SA * 2);

    const int tid  = threadIdx.x;
    const int lane = tid & 31;
    const int warp = tid >> 5;
    const int g    = lane >> 2;
    const int tg   = lane & 3;
    const int wm   = warp >> 1;      // 32-row band
    const int wn   = warp & 1;       // 64-col band

    const int uStart = (int)(((long long)blockIdx.x       * NUNITS) / GRID);
    const int uEnd   = (int)(((long long)(blockIdx.x + 1) * NUNITS) / GRID);

    // ldmatrix lane-address bases (byte offsets into tile, lane-dependent)
    const uint32_t asBase = (uint32_t)__cvta_generic_to_shared(As);
    const uint32_t b0Base = (uint32_t)__cvta_generic_to_shared(B0);
    const uint32_t b1Base = (uint32_t)__cvta_generic_to_shared(B1);
    const uint32_t lmCol  = (uint32_t)((lane >> 4) * 8) * 2;   // 8-col half select
    uint32_t aOff[2], bOff[4];
#pragma unroll
    for (int mi = 0; mi < 2; mi++)
        aOff[mi] = (uint32_t)((wm * 32 + mi * 16 + (lane & 15)) * SA) * 2 + lmCol;
#pragma unroll
    for (int p = 0; p < 4; p++)
        bOff[p] = (uint32_t)((wn * 64 + p * 16 + (lane & 15)) * SA) * 2 + lmCol;

    // prologue: A(rt0) + B(u0) -> buf0
    {
        int rt0 = uStart >> 5, ch0 = uStart & 31;
#pragma unroll
        for (int i = 0; i < 16; i++) {
            int idx = i * 256 + tid;
            int r = idx >> 5, q = idx & 31;
            cp16(&As[r * SA + q * 8], &g_fn[(size_t)(rt0 * BM + r) * DD + q * 8]);
            cp16(&B0[r * SA + q * 8], &g_fn[(size_t)(ch0 * BN + r) * DD + q * 8]);
        }
        cp_commit();
    }

    const int jsel   = (tg & 1) * 2;              // word pair {jsel, jsel+1}
    const int bshift0 = wn * 16 + (tg >> 1);      // bit base for ni=0
    const uint32_t cntM = 0x5555u << bshift0;     // this thread's 8 even-ni bits per word

    for (int u = uStart; u < uEnd; u++) {
        const int rt = u >> 5, ch = u & 31;
        const int rowBase = rt * BM;
        const bool odd = (u - uStart) & 1;
        const uint32_t bcB = odd ? b1Base : b0Base;
        __nv_bfloat16* Bn  = odd ? B0 : B1;

        cp_wait_all();
        __syncthreads();

        const bool hasNext = (u + 1 < uEnd);
        const int  nrt = (u + 1) >> 5, nch = (u + 1) & 31;

        if (hasNext && nrt == rt) {
#pragma unroll
            for (int i = 0; i < 16; i++) {
                int idx = i * 256 + tid;
                int r = idx >> 5, q = idx & 31;
                cp16(&Bn[r * SA + q * 8], &g_fn[(size_t)(nch * BN + r) * DD + q * 8]);
            }
            cp_commit();
        }

        // --- 128x128x256 MMA; ldmatrix.x4 fragment loads ---
        float acc[2][8][4];
#pragma unroll
        for (int mi = 0; mi < 2; mi++)
#pragma unroll
            for (int ni = 0; ni < 8; ni++)
#pragma unroll
                for (int k = 0; k < 4; k++) acc[mi][ni][k] = 0.f;

#pragma unroll 4
        for (int kb = 0; kb < DD; kb += 16) {
            const uint32_t kbB = (uint32_t)kb * 2;
            uint32_t a[2][4];
#pragma unroll
            for (int mi = 0; mi < 2; mi++)
                ldsm_x4(a[mi][0], a[mi][1], a[mi][2], a[mi][3], asBase + aOff[mi] + kbB);
            uint32_t br[4][4];
#pragma unroll
            for (int p = 0; p < 4; p++)
                ldsm_x4(br[p][0], br[p][1], br[p][2], br[p][3], bcB + bOff[p] + kbB);
#pragma unroll
            for (int ni = 0; ni < 8; ni++) {
                uint32_t b0 = br[ni >> 1][ni & 1];
                uint32_t b1 = br[ni >> 1][(ni & 1) + 2];
#pragma unroll
                for (int mi = 0; mi < 2; mi++) {
                    asm volatile(
                        "mma.sync.aligned.m16n8k16.row.col.f32.bf16.bf16.f32 "
                        "{%0,%1,%2,%3}, {%4,%5,%6,%7}, {%8,%9}, {%0,%1,%2,%3};"
                        : "+f"(acc[mi][ni][0]), "+f"(acc[mi][ni][1]),
                          "+f"(acc[mi][ni][2]), "+f"(acc[mi][ni][3])
                        : "r"(a[mi][0]), "r"(a[mi][1]), "r"(a[mi][2]), "r"(a[mi][3]),
                          "r"(b0), "r"(b1));
                }
            }
        }

        if (hasNext && nrt != rt) {
            __syncthreads();           // uniform: all warps done reading As
#pragma unroll
            for (int i = 0; i < 16; i++) {
                int idx = i * 256 + tid;
                int r = idx >> 5, q = idx & 31;
                cp16(&As[r * SA + q * 8], &g_fn[(size_t)(nrt * BM + r) * DD + q * 8]);
                cp16(&Bn[r * SA + q * 8], &g_fn[(size_t)(nch * BN + r) * DD + q * 8]);
            }
            cp_commit();
        }

        // --- epilogue: 4 row-contexts; strided bit layout; one LDG.64 per mask ---
#pragma unroll
        for (int mi = 0; mi < 2; mi++) {
#pragma unroll
            for (int h = 0; h < 2; h++) {
                int r  = wm * 32 + mi * 16 + h * 8 + g;
                int ig = rowBase + r;
                int wbase = ig * 128 + ch * 4 + jsel;
                uint2 pw = *(const uint2*)&g_pmBits[wbase];   // {word jsel, jsel+1}
                uint2 nw = *(const uint2*)&g_nmBits[wbase];
                int d = ig - ch * 128;                        // diagonal col in chunk
                if ((unsigned)d < 128u) {
                    int dj = d & 3;
                    uint32_t clr = ~(1u << (d >> 2));
                    if (dj == jsel)     { pw.x &= clr; nw.x &= clr; }
                    if (dj == jsel + 1) { pw.y &= clr; nw.y &= clr; }
                }
                float cnt = (float)(__popc(pw.x & cntM) + __popc(pw.y & cntM));
                float neg = 0.f, pcs = 0.f;
#pragma unroll
                for (int ni = 0; ni < 8; ni++) {
                    int bs = bshift0 + ni * 2;
                    float c0 = acc[mi][ni][h * 2 + 0] * INV_T;
                    float c1 = acc[mi][ni][h * 2 + 1] * INV_T;
                    float e0 = fast_expf(c0);
                    float e1 = fast_expf(c1);
                    if ((nw.x >> bs) & 1) neg += e0;
                    if ((nw.y >> bs) & 1) neg += e1;
                    if ((pw.x >> bs) & 1) pcs += c0;
                    if ((pw.y >> bs) & 1) pcs += c1;
                }
                neg += __shfl_xor_sync(0xffffffffu, neg, 1);
                pcs += __shfl_xor_sync(0xffffffffu, pcs, 1);
                cnt += __shfl_xor_sync(0xffffffffu, cnt, 1);
                neg += __shfl_xor_sync(0xffffffffu, neg, 2);
                pcs += __shfl_xor_sync(0xffffffffu, pcs, 2);
                cnt += __shfl_xor_sync(0xffffffffu, cnt, 2);
                if (tg == 0) {
                    int slot = (ch * 2 + wn) * NN + ig;
                    g_negP[slot] = neg;
                    g_pcsP[slot] = pcs;
                    g_cntP[slot] = cnt;
                }
            }
        }
    }
}

// ---------------------------------------------------------------------------
// Kernel 3: per-row loss + block reduce; last-done block sums 16 partials.
// ---------------------------------------------------------------------------
__global__ void __launch_bounds__(256) rowloss_kernel(float* __restrict__ out) {
    __shared__ float red[256];
    int i = blockIdx.x * 256 + threadIdx.x;
    float neg = 0.f, pcs = 0.f, cnt = 0.f;
#pragma unroll 8
    for (int s = 0; s < NCHUNKS * 2; s++) {
        neg += g_negP[s * NN + i];
        pcs += g_pcsP[s * NN + i];
        cnt += g_cntP[s * NN + i];
    }
    float t = 0.f;
    if (cnt > 0.f) t = (pcs - cnt * logf(fmaxf(neg, 1e-30f))) / cnt;
    red[threadIdx.x] = t;
    __syncthreads();
    for (int o = 128; o; o >>= 1) {
        if (threadIdx.x < o) red[threadIdx.x] += red[threadIdx.x + o];
        __syncthreads();
    }
    if (threadIdx.x == 0) {
        g_blockSum[blockIdx.x] = red[0];
        __threadfence();
        unsigned old = atomicInc(&g_ctr, 15u);   // wraps to 0 after 16th arrival
        if (old == 15u) {
            float v = 0.f;
#pragma unroll
            for (int b = 0; b < 16; b++) v += g_blockSum[b];
            out[0] = -v / (float)NN;
        }
    }
}

// ---------------------------------------------------------------------------
extern "C" void kernel_launch(void* const* d_in, const int* in_sizes, int n_in,
                              void* d_out, int out_size) {
    const float* feat = (const float*)d_in[0];
    const float* pm   = (const float*)d_in[1];
    const float* nm   = (const float*)d_in[2];
    float* out = (float*)d_out;

    cudaFuncSetAttribute(ssntx_main_kernel,
                         cudaFuncAttributeMaxDynamicSharedMemorySize, 202752);

    prep_kernel<<<1024, 256>>>(feat, pm, nm);
    ssntx_main_kernel<<<GRID, 256, 202752>>>();
    rowloss_kernel<<<16, 256>>>(out);
}

// round 12
// speedup vs baseline: 1.2476x; 1.2476x over previous
#include <cuda_runtime.h>
#include <cuda_bf16.h>
#include <stdint.h>

#define NN 4096
#define DD 256
#define BM 128
#define BN 128
#define SA 264          // bf16 elems per padded smem row (256+8)
#define NCHUNKS 32
#define NROWT   32
#define NUNITS  (NCHUNKS * NROWT)
#define GRID 148
#define INV_T 14.285714285714286f

// smem map: A | B0 | B1 | bit tiles (2 bufs x 2 masks x 512 words)
#define BITS_OFF 202752
#define SMEM_TOTAL (202752 + 8192)

// scratch (no allocations allowed -> device globals)
__device__ __nv_bfloat16 g_fn[NN * DD];
__device__ float g_negP[NCHUNKS * 2 * NN];
__device__ float g_pcsP[NCHUNKS * 2 * NN];
__device__ float g_cntP[NCHUNKS * 2 * NN];
__device__ float g_blockSum[16];
__device__ unsigned g_ctr = 0;   // self-resetting via atomicInc wrap

// ---------------------------------------------------------------------------
__device__ __forceinline__ float fast_expf(float x) {
    float y = x * 1.4426950408889634f;
    float n = rintf(y);
    float f = y - n;
    float p = 1.3333558146e-3f;
    p = fmaf(p, f, 9.6181291076e-3f);
    p = fmaf(p, f, 5.5504108664e-2f);
    p = fmaf(p, f, 2.4022650696e-1f);
    p = fmaf(p, f, 6.9314718056e-1f);
    p = fmaf(p, f, 1.0f);
    int ni = (int)n;
    return p * __int_as_float((ni + 127) << 23);
}

__device__ __forceinline__ void cp16(void* s, const void* g) {
    uint32_t sa = (uint32_t)__cvta_generic_to_shared(s);
    asm volatile("cp.async.cg.shared.global [%0], [%1], 16;\n" :: "r"(sa), "l"(g));
}
__device__ __forceinline__ void cp_commit()  { asm volatile("cp.async.commit_group;\n" ::: "memory"); }
__device__ __forceinline__ void cp_wait_all(){ asm volatile("cp.async.wait_group 0;\n" ::: "memory"); }

__device__ __forceinline__ void ldsm_x4(uint32_t& r0, uint32_t& r1, uint32_t& r2,
                                        uint32_t& r3, uint32_t saddr) {
    asm volatile("ldmatrix.sync.aligned.m8n8.x4.shared.b16 {%0,%1,%2,%3}, [%4];"
                 : "=r"(r0), "=r"(r1), "=r"(r2), "=r"(r3) : "r"(saddr));
}

// ---- mask pack waves: 32 steps (s>>4: mask, s&15: row-iter); warp w owns rows w*16.. ----
// bit layout per unit tile: word (rowLocal*4 + j), bit b <=> col colBase + b*4 + j
__device__ __forceinline__ void pack_issue(float4* pk, const float* pmask,
                                           const float* nmask, int w0,
                                           int rowBase, int colBase, int warp, int lane) {
#pragma unroll
    for (int k = 0; k < 8; k++) {
        int s = w0 + k;
        const float* base = (s & 16) ? nmask : pmask;
        const float* src = base + (size_t)(rowBase + warp * 16 + (s & 15)) * NN
                         + colBase + lane * 4;
        pk[k] = __ldcs((const float4*)src);
    }
}
__device__ __forceinline__ void pack_consume(const float4* pk, uint32_t* bits,
                                             int w0, int warp, int lane) {
#pragma unroll
    for (int k = 0; k < 8; k++) {
        int s = w0 + k;
        uint32_t b0 = __ballot_sync(0xffffffffu, pk[k].x != 0.f);
        uint32_t b1 = __ballot_sync(0xffffffffu, pk[k].y != 0.f);
        uint32_t b2 = __ballot_sync(0xffffffffu, pk[k].z != 0.f);
        uint32_t b3 = __ballot_sync(0xffffffffu, pk[k].w != 0.f);
        if (lane == 0) {
            int m = (s >> 4) & 1, i = s & 15;
            *(uint4*)&bits[m * 512 + (warp * 16 + i) * 4] = make_uint4(b0, b1, b2, b3);
        }
    }
}

// ---------------------------------------------------------------------------
// Kernel 1: row-normalize features -> bf16 (masks handled inside main kernel)
// ---------------------------------------------------------------------------
__global__ void __launch_bounds__(256) normalize_kernel(const float* __restrict__ f) {
    int row  = blockIdx.x * 8 + (threadIdx.x >> 5);
    int lane = threadIdx.x & 31;
    const float4* src = (const float4*)(f + (size_t)row * DD);
    float4 v0 = src[lane * 2];
    float4 v1 = src[lane * 2 + 1];
    float ss = v0.x * v0.x;
    ss = fmaf(v0.y, v0.y, ss); ss = fmaf(v0.z, v0.z, ss); ss = fmaf(v0.w, v0.w, ss);
    ss = fmaf(v1.x, v1.x, ss); ss = fmaf(v1.y, v1.y, ss);
    ss = fmaf(v1.z, v1.z, ss); ss = fmaf(v1.w, v1.w, ss);
#pragma unroll
    for (int o = 16; o; o >>= 1) ss += __shfl_xor_sync(0xffffffffu, ss, o);
    float s = 1.0f / fmaxf(sqrtf(ss), 1e-8f);
    __nv_bfloat162 h[4];
    h[0] = __floats2bfloat162_rn(v0.x * s, v0.y * s);
    h[1] = __floats2bfloat162_rn(v0.z * s, v0.w * s);
    h[2] = __floats2bfloat162_rn(v1.x * s, v1.y * s);
    h[3] = __floats2bfloat162_rn(v1.z * s, v1.w * s);
    *(uint4*)&g_fn[(size_t)row * DD + lane * 8] = *(uint4*)h;
}

// ---------------------------------------------------------------------------
// Kernel 2: persistent mma.sync GEMM; masks packed in-kernel (own-region
// partition), pipelined under the MMA in 4 LDG waves -> smem bit tiles.
// ---------------------------------------------------------------------------
__global__ void __launch_bounds__(256, 1)
ssntx_main_kernel(const float* __restrict__ pmask, const float* __restrict__ nmask) {
    extern __shared__ unsigned char smem[];
    __nv_bfloat16* As = (__nv_bfloat16*)smem;
    __nv_bfloat16* B0 = (__nv_bfloat16*)(smem + BM * SA * 2);
    __nv_bfloat16* B1 = (__nv_bfloat16*)(smem + 2 * BM * SA * 2);
    uint32_t* bitsAll = (uint32_t*)(smem + BITS_OFF);   // [buf][mask][512 words]

    const int tid  = threadIdx.x;
    const int lane = tid & 31;
    const int warp = tid >> 5;
    const int g    = lane >> 2;
    const int tg   = lane & 3;
    const int wm   = warp >> 1;
    const int wn   = warp & 1;

    const int uStart = (int)(((long long)blockIdx.x       * NUNITS) / GRID);
    const int uEnd   = (int)(((long long)(blockIdx.x + 1) * NUNITS) / GRID);

    const uint32_t asBase = (uint32_t)__cvta_generic_to_shared(As);
    const uint32_t b0Base = (uint32_t)__cvta_generic_to_shared(B0);
    const uint32_t b1Base = (uint32_t)__cvta_generic_to_shared(B1);
    const uint32_t lmCol  = (uint32_t)((lane >> 4) * 8) * 2;
    uint32_t aOff[2], bOff[4];
#pragma unroll
    for (int mi = 0; mi < 2; mi++)
        aOff[mi] = (uint32_t)((wm * 32 + mi * 16 + (lane & 15)) * SA) * 2 + lmCol;
#pragma unroll
    for (int p = 0; p < 4; p++)
        bOff[p] = (uint32_t)((wn * 64 + p * 16 + (lane & 15)) * SA) * 2 + lmCol;

    // prologue: A(rt0) + B(u0) cp.async; pack bits(u0) -> buf0 (latency exposed once)
    {
        int rt0 = uStart >> 5, ch0 = uStart & 31;
#pragma unroll
        for (int i = 0; i < 16; i++) {
            int idx = i * 256 + tid;
            int r = idx >> 5, q = idx & 31;
            cp16(&As[r * SA + q * 8], &g_fn[(size_t)(rt0 * BM + r) * DD + q * 8]);
            cp16(&B0[r * SA + q * 8], &g_fn[(size_t)(ch0 * BN + r) * DD + q * 8]);
        }
        cp_commit();
        float4 pk[8];
#pragma unroll
        for (int w0 = 0; w0 < 32; w0 += 8) {
            pack_issue(pk, pmask, nmask, w0, rt0 * BM, ch0 * BN, warp, lane);
            pack_consume(pk, bitsAll, w0, warp, lane);
        }
    }

    const int jsel    = (tg & 1) * 2;
    const int bshift0 = wn * 16 + (tg >> 1);
    const uint32_t cntM = 0x5555u << bshift0;

    for (int u = uStart; u < uEnd; u++) {
        const int rt = u >> 5, ch = u & 31;
        const int rowBase = rt * BM;
        const int buf = (u - uStart) & 1;
        const uint32_t bcB = buf ? b1Base : b0Base;
        __nv_bfloat16* Bn  = buf ? B0 : B1;
        uint32_t* bitsC = bitsAll + buf * 1024;
        uint32_t* bitsN = bitsAll + (buf ^ 1) * 1024;

        cp_wait_all();
        __syncthreads();   // tiles + bit STS visible; prior epilogue done with bitsN

        const bool hasNext = (u + 1 < uEnd);
        const int  nrt = (u + 1) >> 5, nch = (u + 1) & 31;

        if (hasNext && nrt == rt) {
#pragma unroll
            for (int i = 0; i < 16; i++) {
                int idx = i * 256 + tid;
                int r = idx >> 5, q = idx & 31;
                cp16(&Bn[r * SA + q * 8], &g_fn[(size_t)(nch * BN + r) * DD + q * 8]);
            }
            cp_commit();
        }

        // --- MMA with mask-pack waves for u+1 interleaved at k-quarters ---
        float acc[2][8][4];
#pragma unroll
        for (int mi = 0; mi < 2; mi++)
#pragma unroll
            for (int ni = 0; ni < 8; ni++)
#pragma unroll
                for (int k = 0; k < 4; k++) acc[mi][ni][k] = 0.f;

        float4 pk[8];
        if (hasNext) pack_issue(pk, pmask, nmask, 0, nrt * BM, nch * BN, warp, lane);

#pragma unroll
        for (int kq = 0; kq < 4; kq++) {
#pragma unroll
            for (int kb2 = 0; kb2 < 4; kb2++) {
                const uint32_t kbB = (uint32_t)(kq * 64 + kb2 * 16) * 2;
                uint32_t a[2][4];
#pragma unroll
                for (int mi = 0; mi < 2; mi++)
                    ldsm_x4(a[mi][0], a[mi][1], a[mi][2], a[mi][3], asBase + aOff[mi] + kbB);
                uint32_t br[4][4];
#pragma unroll
                for (int p = 0; p < 4; p++)
                    ldsm_x4(br[p][0], br[p][1], br[p][2], br[p][3], bcB + bOff[p] + kbB);
#pragma unroll
                for (int ni = 0; ni < 8; ni++) {
                    uint32_t b0 = br[ni >> 1][ni & 1];
                    uint32_t b1 = br[ni >> 1][(ni & 1) + 2];
#pragma unroll
                    for (int mi = 0; mi < 2; mi++) {
                        asm volatile(
                            "mma.sync.aligned.m16n8k16.row.col.f32.bf16.bf16.f32 "
                            "{%0,%1,%2,%3}, {%4,%5,%6,%7}, {%8,%9}, {%0,%1,%2,%3};"
                            : "+f"(acc[mi][ni][0]), "+f"(acc[mi][ni][1]),
                              "+f"(acc[mi][ni][2]), "+f"(acc[mi][ni][3])
                            : "r"(a[mi][0]), "r"(a[mi][1]), "r"(a[mi][2]), "r"(a[mi][3]),
                              "r"(b0), "r"(b1));
                    }
                }
            }
            if (hasNext) {
                pack_consume(pk, bitsN, kq * 8, warp, lane);
                if (kq < 3)
                    pack_issue(pk, pmask, nmask, (kq + 1) * 8, nrt * BM, nch * BN, warp, lane);
            }
        }

        if (hasNext && nrt != rt) {
            __syncthreads();   // uniform: all warps done reading As
#pragma unroll
            for (int i = 0; i < 16; i++) {
                int idx = i * 256 + tid;
                int r = idx >> 5, q = idx & 31;
                cp16(&As[r * SA + q * 8], &g_fn[(size_t)(nrt * BM + r) * DD + q * 8]);
                cp16(&Bn[r * SA + q * 8], &g_fn[(size_t)(nch * BN + r) * DD + q * 8]);
            }
            cp_commit();
        }

        // --- epilogue: bits from smem (unit-local layout) ---
#pragma unroll
        for (int mi = 0; mi < 2; mi++) {
#pragma unroll
            for (int h = 0; h < 2; h++) {
                int r  = wm * 32 + mi * 16 + h * 8 + g;
                int ig = rowBase + r;
                uint2 pw = *(const uint2*)&bitsC[r * 4 + jsel];
                uint2 nw = *(const uint2*)&bitsC[512 + r * 4 + jsel];
                int d = ig - ch * 128;
                if ((unsigned)d < 128u) {
                    int dj = d & 3;
                    uint32_t clr = ~(1u << (d >> 2));
                    if (dj == jsel)     { pw.x &= clr; nw.x &= clr; }
                    if (dj == jsel + 1) { pw.y &= clr; nw.y &= clr; }
                }
                float cnt = (float)(__popc(pw.x & cntM) + __popc(pw.y & cntM));
                float neg = 0.f, pcs = 0.f;
#pragma unroll
                for (int ni = 0; ni < 8; ni++) {
                    int bs = bshift0 + ni * 2;
                    float c0 = acc[mi][ni][h * 2 + 0] * INV_T;
                    float c1 = acc[mi][ni][h * 2 + 1] * INV_T;
                    float e0 = fast_expf(c0);
                    float e1 = fast_expf(c1);
                    if ((nw.x >> bs) & 1) neg += e0;
                    if ((nw.y >> bs) & 1) neg += e1;
                    if ((pw.x >> bs) & 1) pcs += c0;
                    if ((pw.y >> bs) & 1) pcs += c1;
                }
                neg += __shfl_xor_sync(0xffffffffu, neg, 1);
                pcs += __shfl_xor_sync(0xffffffffu, pcs, 1);
                cnt += __shfl_xor_sync(0xffffffffu, cnt, 1);
                neg += __shfl_xor_sync(0xffffffffu, neg, 2);
                pcs += __shfl_xor_sync(0xffffffffu, pcs, 2);
                cnt += __shfl_xor_sync(0xffffffffu, cnt, 2);
                if (tg == 0) {
                    int slot = (ch * 2 + wn) * NN + ig;
                    g_negP[slot] = neg;
                    g_pcsP[slot] = pcs;
                    g_cntP[slot] = cnt;
                }
            }
        }
    }
}

// ---------------------------------------------------------------------------
// Kernel 3: per-row loss + block reduce; last-done block sums 16 partials.
// ---------------------------------------------------------------------------
__global__ void __launch_bounds__(256) rowloss_kernel(float* __restrict__ out) {
    __shared__ float red[256];
    int i = blockIdx.x * 256 + threadIdx.x;
    float neg = 0.f, pcs = 0.f, cnt = 0.f;
#pragma unroll 8
    for (int s = 0; s < NCHUNKS * 2; s++) {
        neg += g_negP[s * NN + i];
        pcs += g_pcsP[s * NN + i];
        cnt += g_cntP[s * NN + i];
    }
    float t = 0.f;
    if (cnt > 0.f) t = (pcs - cnt * logf(fmaxf(neg, 1e-30f))) / cnt;
    red[threadIdx.x] = t;
    __syncthreads();
    for (int o = 128; o; o >>= 1) {
        if (threadIdx.x < o) red[threadIdx.x] += red[threadIdx.x + o];
        __syncthreads();
    }
    if (threadIdx.x == 0) {
        g_blockSum[blockIdx.x] = red[0];
        __threadfence();
        unsigned old = atomicInc(&g_ctr, 15u);   // wraps to 0 after 16th arrival
        if (old == 15u) {
            float v = 0.f;
#pragma unroll
            for (int b = 0; b < 16; b++) v += g_blockSum[b];
            out[0] = -v / (float)NN;
        }
    }
}

// ---------------------------------------------------------------------------
extern "C" void kernel_launch(void* const* d_in, const int* in_sizes, int n_in,
                              void* d_out, int out_size) {
    const float* feat = (const float*)d_in[0];
    const float* pm   = (const float*)d_in[1];
    const float* nm   = (const float*)d_in[2];
    float* out = (float*)d_out;

    cudaFuncSetAttribute(ssntx_main_kernel,
                         cudaFuncAttributeMaxDynamicSharedMemorySize, SMEM_TOTAL);

    normalize_kernel<<<NN / 8, 256>>>(feat);
    ssntx_main_kernel<<<GRID, 256, SMEM_TOTAL>>>(pm, nm);
    rowloss_kernel<<<16, 256>>>(out);
}